// round 6
// baseline (speedup 1.0000x reference)
#include <cuda_runtime.h>
#include <math.h>
#include <stdint.h>

#define BATCH 512
#define DIN   128
#define HIDN  256
#define CSIZE 4
#define BC    16
#define CPC   64
#define NCTA  128
#define NT    512
#define KSPL  8

// smem layout (float offsets)
#define OFF_HID0 0            /* [16][256][2] dup hidden buf0 : 32KB */
#define OFF_HID1 8192         /* buf1                         : 32KB */
#define OFF_X    16384        /* [16][128] x_t                :  8KB */
#define OFF_PAH  18432        /* ull [8][16][64] (A,H)        : 64KB */
#define OFF_PX   34816        /* float [8][16][64] X          : 32KB */
#define SMEM_FLOATS 43008
#define SMEM_BYTES  (SMEM_FLOATS * 4)   /* 172032 */

typedef unsigned long long ull;

__device__ __forceinline__ ull ffma2(ull a, ull b, ull c) {
    ull d;
    asm("fma.rn.f32x2 %0, %1, %2, %3;" : "=l"(d) : "l"(a), "l"(b), "l"(c));
    return d;
}
__device__ __forceinline__ ull add2(ull a, ull b) {
    ull d;
    asm("add.rn.f32x2 %0, %1, %2;" : "=l"(d) : "l"(a), "l"(b));
    return d;
}
__device__ __forceinline__ ull pack2(float x, float y) {
    ull d;
    asm("mov.b64 %0, {%1, %2};" : "=l"(d) : "f"(x), "f"(y));
    return d;
}
__device__ __forceinline__ void unpack2(ull a, float& x, float& y) {
    asm("mov.b64 {%0, %1}, %2;" : "=f"(x), "=f"(y) : "l"(a));
}
__device__ __forceinline__ uint32_t smem_u32(const void* p) {
    uint32_t a;
    asm("{ .reg .u64 t; cvta.to.shared.u64 t, %1; cvt.u32.u64 %0, t; }"
        : "=r"(a) : "l"(p));
    return a;
}
__device__ __forceinline__ void cluster_sync_() {
    asm volatile("barrier.cluster.arrive.aligned;" ::: "memory");
    asm volatile("barrier.cluster.wait.aligned;" ::: "memory");
}

__global__ __launch_bounds__(NT, 1) __cluster_dims__(CSIZE, 1, 1)
void rnn_kernel(const float* __restrict__ data,
                const float* __restrict__ ih_w,
                const float* __restrict__ ih_b,
                const float* __restrict__ hh_w,
                const float* __restrict__ hh_b,
                const int*   __restrict__ lengths,
                float*       __restrict__ out)
{
    extern __shared__ float smem[];
    float* s_x   = smem + OFF_X;
    ull*   s_pAH = (ull*)(smem + OFF_PAH);
    float* s_pX  = smem + OFF_PX;

    const int tid = threadIdx.x;
    uint32_t r;
    asm("mov.u32 %0, %%cluster_ctarank;" : "=r"(r));
    const int B0  = (blockIdx.x >> 2) * BC;
    const int cl  = tid & 63;          // owned column (local)
    const int kq  = tid >> 6;          // k-eighth 0..7
    const int gc  = (int)r * CPC + cl; // global column
    const int k0  = kq * 32;           // hh k range [k0, k0+32)
    const int ik0 = kq * 16;           // ih k range [ik0, ik0+16)

    // ---- persistent register weights ----
    ull whh2[32];                      // (wA[k], wH[k]) for col gc
    #pragma unroll
    for (int i = 0; i < 32; i++) {
        float wa = hh_w[gc * HIDN + k0 + i];
        float wh = hh_w[(gc + HIDN) * HIDN + k0 + i];
        whh2[i] = pack2(wa, wh);
    }
    float wih_r[16];
    #pragma unroll
    for (int i = 0; i < 16; i++) wih_r[i] = ih_w[gc * DIN + ik0 + i];

    // zero both hidden buffers
    for (int i = tid; i < 16384; i += NT) smem[i] = 0.0f;

    const float bA = hh_b[gc];
    const float bH = hh_b[gc + HIDN];
    const float bX = ih_b[gc];

    int len2[2];
    #pragma unroll
    for (int j = 0; j < 2; j++) len2[j] = lengths[B0 + kq * 2 + j];
    int cap = 1;
    for (int i = 0; i < BC; i++) cap = max(cap, lengths[B0 + i]);

    // remote hidden bases (buffer0); buffer1 = +32768 bytes
    uint32_t h0 = smem_u32(smem);
    uint32_t rb[CSIZE];
    #pragma unroll
    for (int d = 0; d < CSIZE; d++)
        asm("mapa.shared::cluster.u32 %0, %1, %2;" : "=r"(rb[d]) : "r"(h0), "r"(d));

    __syncthreads();
    cluster_sync_();   // all CTAs zeroed before any remote write

    // prefetch x(0): one float4 per thread covers 16*128 floats
    float4 xp;
    {
        const float4* src = (const float4*)(data + ((size_t)0 * BATCH + B0) * DIN);
        xp = src[tid];
    }

    for (int t = 0; t < cap; ++t) {
        const float* cur = smem + ((t & 1) ? OFF_HID1 : OFF_HID0);
        const uint32_t nxtoff = ((t + 1) & 1) * 32768u;

        // stage x_t
        ((float4*)s_x)[tid] = xp;
        __syncthreads();
        if (t + 1 < cap) {
            const float4* src = (const float4*)(data + ((size_t)(t + 1) * BATCH + B0) * DIN);
            xp = src[tid];
        }

        // ---- compute partials for all 16 batches ----
        #pragma unroll 2
        for (int b = 0; b < 16; b++) {
            const float* hb = cur + b * 512 + k0 * 2;   // 32 dup pairs = 16 x 16B
            ull a0 = 0ull, a1 = 0ull, a2 = 0ull, a3 = 0ull;
            #pragma unroll
            for (int i = 0; i < 16; i++) {
                ulonglong2 hd = *(const ulonglong2*)(hb + 4 * i);
                if (i & 1) {
                    a2 = ffma2(hd.x, whh2[2 * i],     a2);
                    a3 = ffma2(hd.y, whh2[2 * i + 1], a3);
                } else {
                    a0 = ffma2(hd.x, whh2[2 * i],     a0);
                    a1 = ffma2(hd.y, whh2[2 * i + 1], a1);
                }
            }
            const float* xb = s_x + b * 128 + ik0;
            float x0 = 0.f, x1 = 0.f, x2 = 0.f, x3 = 0.f;
            #pragma unroll
            for (int i = 0; i < 4; i++) {
                float4 xv = *(const float4*)(xb + 4 * i);
                x0 = fmaf(xv.x, wih_r[4 * i + 0], x0);
                x1 = fmaf(xv.y, wih_r[4 * i + 1], x1);
                x2 = fmaf(xv.z, wih_r[4 * i + 2], x2);
                x3 = fmaf(xv.w, wih_r[4 * i + 3], x3);
            }
            s_pAH[(kq * 16 + b) * 64 + cl] = add2(add2(a0, a2), add2(a1, a3));
            s_pX [(kq * 16 + b) * 64 + cl] = (x0 + x1) + (x2 + x3);
        }
        __syncthreads();   // partials visible CTA-locally

        // ---- epilogue: thread finalizes batches kq*2, kq*2+1 at col cl ----
        float wval[2];
        #pragma unroll
        for (int j = 0; j < 2; j++) {
            int b = kq * 2 + j;
            ull sAH = s_pAH[(0 * 16 + b) * 64 + cl];
            float sX = s_pX[(0 * 16 + b) * 64 + cl];
            #pragma unroll
            for (int q = 1; q < KSPL; q++) {
                sAH = add2(sAH, s_pAH[(q * 16 + b) * 64 + cl]);
                sX += s_pX[(q * 16 + b) * 64 + cl];
            }
            float A, H;
            unpack2(sAH, A, H);
            A += bA; H += bH;
            float alpha = 1.0f / (1.0f + expf(-A));
            float hs    = (exp2f(alpha * H) - 1.0f) / alpha + alpha;
            float nh    = tanhf(sX + bX + hs);
            float oldv  = cur[b * 512 + 2 * gc];          // carry-over for masked rows
            wval[j] = (t < len2[j]) ? nh : oldv;
        }

        // ---- broadcast (dup) to next buffer of all 4 CTAs ----
        #pragma unroll
        for (int j = 0; j < 2; j++) {
            uint32_t v = __float_as_uint(wval[j]);
            ull v2;
            asm("mov.b64 %0, {%1, %1};" : "=l"(v2) : "r"(v));
            uint32_t boff = nxtoff + (uint32_t)(((kq * 2 + j) * 512 + 2 * gc) * 4);
            #pragma unroll
            for (int d = 0; d < CSIZE; d++) {
                asm volatile("st.shared::cluster.u64 [%0], %1;"
                             :: "r"(rb[d] + boff), "l"(v2) : "memory");
            }
        }
        cluster_sync_();   // writes visible before next step's reads
    }

    // final state lives in buffer (cap & 1)
    const float* fin = smem + ((cap & 1) ? OFF_HID1 : OFF_HID0);
    #pragma unroll
    for (int j = 0; j < 2; j++) {
        int b = kq * 2 + j;
        out[(size_t)(B0 + b) * HIDN + gc] = fin[b * 512 + 2 * gc];
    }
}

extern "C" void kernel_launch(void* const* d_in, const int* in_sizes, int n_in,
                              void* d_out, int out_size)
{
    (void)in_sizes; (void)n_in; (void)out_size;
    const float* data    = (const float*)d_in[0];   // [1024,512,128]
    const float* ih_w    = (const float*)d_in[1];   // [256,128]
    const float* ih_b    = (const float*)d_in[2];   // [256]
    const float* hh_w    = (const float*)d_in[3];   // [512,256]
    const float* hh_b    = (const float*)d_in[4];   // [512]
    const int*   lengths = (const int*)d_in[5];     // [512]
    float*       out     = (float*)d_out;           // [1,512,256]

    cudaFuncSetAttribute(rnn_kernel,
                         cudaFuncAttributeMaxDynamicSharedMemorySize, SMEM_BYTES);
    rnn_kernel<<<NCTA, NT, SMEM_BYTES>>>(data, ih_w, ih_b, hh_w, hh_b, lengths, out);
}